// round 15
// baseline (speedup 1.0000x reference)
#include <cuda_runtime.h>
#include <cuda_fp16.h>

// Problem constants: N=100000, E=3200000, FEAT=128, HID=32, EMB=16
#define NMAX 100000
#define EMAX 3200000
#define EPAD (EMAX + 8 * NMAX + 64)   // per-node pad to multiple of 8 + slack
#define SCAN_B 1024
#define NBLK ((NMAX + SCAN_B - 1) / SCAN_B)   // 98

// ---- scratch (device globals) ----
// +1 row: sentinel node NMAX (never written -> stays zero from module init)
__device__ __align__(16) __half g_h1h[(NMAX + 1) * 32];
__device__ float  g_hp1[NMAX * 32];
__device__ float  g_als1[NMAX + 1], g_ald1[NMAX];
__device__ __align__(16) __half g_h2h[(NMAX + 1) * 16];
__device__ float  g_als2[NMAX + 1], g_ald2[NMAX];

__device__ int g_deg [NMAX + 1];      // [NMAX] = scan arrive counter
__device__ int g_off [NMAX];
__device__ int g_bsum [NBLK];
__device__ unsigned short g_rank[EMAX];
__device__ int g_esrc[EPAD];

__device__ __forceinline__ float leaky(float a) { return a > 0.0f ? a : 0.2f * a; }
__device__ __forceinline__ float2 h2f(unsigned b) {
    __half2 h = *reinterpret_cast<__half2*>(&b);
    return __half22float2(h);
}

// ===========================================================================
// Fused hist + node1.
// ===========================================================================
__global__ __launch_bounds__(256) void hist_node1_kernel(
    const int* __restrict__ dst, int E,
    const float* __restrict__ x, const float* __restrict__ W1,
    const float* __restrict__ asrc, const float* __restrict__ adst, int N, int histB)
{
    if ((int)blockIdx.x < histB) {
        int t = blockIdx.x * 256 + threadIdx.x;
        int e = t * 4;
        if (e + 3 < E) {
            int4 d = *reinterpret_cast<const int4*>(dst + e);
            short4 r;
            r.x = (short)atomicAdd(&g_deg[d.x], 1);
            r.y = (short)atomicAdd(&g_deg[d.y], 1);
            r.z = (short)atomicAdd(&g_deg[d.z], 1);
            r.w = (short)atomicAdd(&g_deg[d.w], 1);
            *reinterpret_cast<short4*>(g_rank + e) = r;
        } else {
            for (; e < E; e++) g_rank[e] = (unsigned short)atomicAdd(&g_deg[__ldg(dst + e)], 1);
        }
        return;
    }

    __shared__ float Ws[128 * 32];
    __shared__ float s_as[32], s_ad[32];
    for (int i = threadIdx.x; i < 128 * 32; i += 256) Ws[i] = W1[i];
    if (threadIdx.x < 32) { s_as[threadIdx.x] = asrc[threadIdx.x]; s_ad[threadIdx.x] = adst[threadIdx.x]; }
    __syncthreads();

    int n = (blockIdx.x - histB) * 256 + threadIdx.x;
    if (n >= N) return;

    float4 acc[8];
#pragma unroll
    for (int i = 0; i < 8; i++) acc[i] = make_float4(0.f, 0.f, 0.f, 0.f);

    const float4* xr = reinterpret_cast<const float4*>(x + (size_t)n * 128);
#pragma unroll 4
    for (int k4 = 0; k4 < 32; k4++) {
        float4 xv = __ldg(&xr[k4]);
        float xk[4] = {xv.x, xv.y, xv.z, xv.w};
#pragma unroll
        for (int kk = 0; kk < 4; kk++) {
            const float4* wr = reinterpret_cast<const float4*>(&Ws[(k4 * 4 + kk) * 32]);
            float xs = xk[kk];
#pragma unroll
            for (int c4 = 0; c4 < 8; c4++) {
                float4 w = wr[c4];
                acc[c4].x = fmaf(xs, w.x, acc[c4].x); acc[c4].y = fmaf(xs, w.y, acc[c4].y);
                acc[c4].z = fmaf(xs, w.z, acc[c4].z); acc[c4].w = fmaf(xs, w.w, acc[c4].w);
            }
        }
    }

    float als = 0.f, ald = 0.f;
#pragma unroll
    for (int c4 = 0; c4 < 8; c4++) {
        float4 a  = acc[c4];
        float4 s4 = reinterpret_cast<const float4*>(s_as)[c4];
        float4 d4 = reinterpret_cast<const float4*>(s_ad)[c4];
        als += a.x*s4.x + a.y*s4.y + a.z*s4.z + a.w*s4.w;
        ald += a.x*d4.x + a.y*d4.y + a.z*d4.z + a.w*d4.w;
    }
    g_als1[n] = als; g_ald1[n] = ald;

    __half2* hp = reinterpret_cast<__half2*>(&g_h1h[n * 32]);
#pragma unroll
    for (int c4 = 0; c4 < 8; c4++) {
        hp[c4 * 2]     = __floats2half2_rn(acc[c4].x, acc[c4].y);
        hp[c4 * 2 + 1] = __floats2half2_rn(acc[c4].z, acc[c4].w);
    }
}

// ===========================================================================
// Fused scan over PADDED degrees (pdeg = round-up-8), grid sync via spin
// (98 resident blocks), writes g_off, fills padding with sentinel N.
// ===========================================================================
__global__ __launch_bounds__(SCAN_B) void scan_kernel(int N, int nb) {
    __shared__ int sh[SCAN_B];
    __shared__ int red[128];
    int b = blockIdx.x;
    int gid = b * SCAN_B + threadIdx.x;
    int deg = (gid < N) ? g_deg[gid] : 0;
    int pv = (deg + 7) & ~7;
    sh[threadIdx.x] = pv;
    __syncthreads();
#pragma unroll
    for (int o = 1; o < SCAN_B; o <<= 1) {
        int t = (threadIdx.x >= o) ? sh[threadIdx.x - o] : 0;
        __syncthreads();
        sh[threadIdx.x] += t;
        __syncthreads();
    }
    if (threadIdx.x == SCAN_B - 1) {
        g_bsum[b] = sh[SCAN_B - 1];
        __threadfence();
        atomicAdd(&g_deg[NMAX], 1);
    }
    if (threadIdx.x == 0) {
        while (((volatile int*)g_deg)[NMAX] < nb) { }
    }
    __syncthreads();
    __threadfence();

    int t = threadIdx.x;
    if (t < 128) red[t] = (t < b) ? g_bsum[t] : 0;
    __syncthreads();
    if (t < 64) red[t] += red[t + 64];
    __syncthreads();
    if (t < 32) {
        int s = red[t] + red[t + 32];
#pragma unroll
        for (int o = 16; o; o >>= 1) s += __shfl_xor_sync(0xffffffffu, s, o);
        if (t == 0) red[0] = s;
    }
    __syncthreads();
    int prev = red[0];

    if (gid < N) {
        int off = prev + sh[threadIdx.x] - pv;
        g_off[gid] = off;
        for (int i = off + deg; i < off + pv; i++) g_esrc[i] = N;
    }
    if (b == 0 && threadIdx.x == 0) {
        g_als1[N] = -1e30f;
        g_als2[N] = -1e30f;
    }
}

// ===========================================================================
// permute: atomic-free. p = off[dst[e]] + rank[e]; esrc[p] = src[e].
// ===========================================================================
__global__ __launch_bounds__(256) void permute_kernel(
    const int* __restrict__ src, const int* __restrict__ dst, int E)
{
    int t = blockIdx.x * 256 + threadIdx.x;
    int e = t * 4;
    if (e + 3 < E) {
        int4 d = *reinterpret_cast<const int4*>(dst + e);
        short4 r = *reinterpret_cast<const short4*>(g_rank + e);
        int4 s = *reinterpret_cast<const int4*>(src + e);
        int p0 = __ldg(&g_off[d.x]) + (int)(unsigned short)r.x;
        int p1 = __ldg(&g_off[d.y]) + (int)(unsigned short)r.y;
        int p2 = __ldg(&g_off[d.z]) + (int)(unsigned short)r.z;
        int p3 = __ldg(&g_off[d.w]) + (int)(unsigned short)r.w;
        g_esrc[p0] = s.x;
        g_esrc[p1] = s.y;
        g_esrc[p2] = s.z;
        g_esrc[p3] = s.w;
    } else {
        for (; e < E; e++) {
            int d = __ldg(dst + e);
            g_esrc[__ldg(&g_off[d]) + (int)g_rank[e]] = __ldg(src + e);
        }
    }
}

// ===========================================================================
// agg1: FOUR nodes per warp, 8 lanes each. Unconditional loads (padding +
// sentinel). __launch_bounds__(256, 8) caps regs at 32 -> occupancy ~83%.
// ===========================================================================
__global__ __launch_bounds__(256, 8) void agg1_kernel(const float* __restrict__ b1, int N)
{
    int wid = (blockIdx.x * 256 + threadIdx.x) >> 5;
    int lane = threadIdx.x & 31;
    int quad = lane >> 3;
    int l8 = lane & 7;
    int n = wid * 4 + quad;
    if (wid * 4 >= N) return;
    bool nvalid = (n < N);
    int nn = nvalid ? n : (N - 1);
    unsigned gmask = 0xFFu << (quad * 8);

    float ald = __ldg(&g_ald1[nn]);
    int start = g_off[nn];
    int deg = nvalid ? g_deg[nn] : 0;
    int nb = (deg + 7) >> 3;

    int s = __ldg(&g_esrc[start + l8]);
    float w = __expf(leaky(__ldg(&g_als1[s]) + ald));

    float4 acc = make_float4(0.f, 0.f, 0.f, 0.f);
    float den = 0.f;
    const uint2* h1u = reinterpret_cast<const uint2*>(g_h1h);
    for (int b = 0; b < nb; b++) {
        int s2 = __ldg(&g_esrc[start + (b + 1) * 8 + l8]);
        float al2 = __ldg(&g_als1[s2]);

        den += w;
#pragma unroll
        for (int j = 0; j < 8; j += 4) {
            int   s0 = __shfl_sync(gmask, s, j,     8);
            int   s1 = __shfl_sync(gmask, s, j + 1, 8);
            int   s2b= __shfl_sync(gmask, s, j + 2, 8);
            int   s3 = __shfl_sync(gmask, s, j + 3, 8);
            float w0 = __shfl_sync(gmask, w, j,     8);
            float w1 = __shfl_sync(gmask, w, j + 1, 8);
            float w2 = __shfl_sync(gmask, w, j + 2, 8);
            float w3 = __shfl_sync(gmask, w, j + 3, 8);
            uint2 v0 = __ldg(&h1u[s0 * 8 + l8]);
            uint2 v1 = __ldg(&h1u[s1 * 8 + l8]);
            uint2 v2b= __ldg(&h1u[s2b* 8 + l8]);
            uint2 v3 = __ldg(&h1u[s3 * 8 + l8]);
            float2 f0a = h2f(v0.x), f0b = h2f(v0.y);
            float2 f1a = h2f(v1.x), f1b = h2f(v1.y);
            float2 f2a = h2f(v2b.x), f2b = h2f(v2b.y);
            float2 f3a = h2f(v3.x), f3b = h2f(v3.y);
            acc.x = fmaf(w0, f0a.x, acc.x); acc.y = fmaf(w0, f0a.y, acc.y);
            acc.z = fmaf(w0, f0b.x, acc.z); acc.w = fmaf(w0, f0b.y, acc.w);
            acc.x = fmaf(w1, f1a.x, acc.x); acc.y = fmaf(w1, f1a.y, acc.y);
            acc.z = fmaf(w1, f1b.x, acc.z); acc.w = fmaf(w1, f1b.y, acc.w);
            acc.x = fmaf(w2, f2a.x, acc.x); acc.y = fmaf(w2, f2a.y, acc.y);
            acc.z = fmaf(w2, f2b.x, acc.z); acc.w = fmaf(w2, f2b.y, acc.w);
            acc.x = fmaf(w3, f3a.x, acc.x); acc.y = fmaf(w3, f3a.y, acc.y);
            acc.z = fmaf(w3, f3b.x, acc.z); acc.w = fmaf(w3, f3b.y, acc.w);
        }
        s = s2;
        w = __expf(leaky(al2 + ald));
    }
#pragma unroll
    for (int o = 4; o; o >>= 1) den += __shfl_xor_sync(0xffffffffu, den, o, 8);

    float wself = __expf(leaky(__ldg(&g_als1[nn]) + ald));
    den += wself;
    {
        uint2 vo = __ldg(&h1u[nn * 8 + l8]);
        float2 fa = h2f(vo.x), fb = h2f(vo.y);
        acc.x = fmaf(wself, fa.x, acc.x); acc.y = fmaf(wself, fa.y, acc.y);
        acc.z = fmaf(wself, fb.x, acc.z); acc.w = fmaf(wself, fb.y, acc.w);
    }

    float inv = 1.0f / (den + 1e-16f);
    if (nvalid) {
        float4 bv = __ldg(&reinterpret_cast<const float4*>(b1)[l8]);
        float4 r;
        r.x = fmaxf(fmaf(acc.x, inv, bv.x), 0.f);
        r.y = fmaxf(fmaf(acc.y, inv, bv.y), 0.f);
        r.z = fmaxf(fmaf(acc.z, inv, bv.z), 0.f);
        r.w = fmaxf(fmaf(acc.w, inv, bv.w), 0.f);
        reinterpret_cast<float4*>(&g_hp1[n * 32])[l8] = r;
    }
}

// ===========================================================================
// node2: h2 = h' @ W2 (-> fp16); al_s2/al_d2
// ===========================================================================
__global__ __launch_bounds__(256) void node2_kernel(
    const float* __restrict__ W2,
    const float* __restrict__ asrc, const float* __restrict__ adst, int N)
{
    __shared__ float Ws[32 * 16];
    __shared__ float s_as[16], s_ad[16];
    for (int i = threadIdx.x; i < 32 * 16; i += 256) Ws[i] = W2[i];
    if (threadIdx.x < 16) { s_as[threadIdx.x] = asrc[threadIdx.x]; s_ad[threadIdx.x] = adst[threadIdx.x]; }
    __syncthreads();

    int n = blockIdx.x * 256 + threadIdx.x;
    if (n >= N) return;

    float4 h2[4];
#pragma unroll
    for (int i = 0; i < 4; i++) h2[i] = make_float4(0.f, 0.f, 0.f, 0.f);

    const float4* hp = reinterpret_cast<const float4*>(&g_hp1[n * 32]);
#pragma unroll
    for (int c4 = 0; c4 < 8; c4++) {
        float4 xv = hp[c4];
        float xk[4] = {xv.x, xv.y, xv.z, xv.w};
#pragma unroll
        for (int kk = 0; kk < 4; kk++) {
            const float4* wr = reinterpret_cast<const float4*>(&Ws[(c4 * 4 + kk) * 16]);
            float xs = xk[kk];
#pragma unroll
            for (int o4 = 0; o4 < 4; o4++) {
                float4 w = wr[o4];
                h2[o4].x = fmaf(xs, w.x, h2[o4].x); h2[o4].y = fmaf(xs, w.y, h2[o4].y);
                h2[o4].z = fmaf(xs, w.z, h2[o4].z); h2[o4].w = fmaf(xs, w.w, h2[o4].w);
            }
        }
    }

    float als = 0.f, ald = 0.f;
#pragma unroll
    for (int o4 = 0; o4 < 4; o4++) {
        float4 a  = h2[o4];
        float4 s4 = reinterpret_cast<const float4*>(s_as)[o4];
        float4 d4 = reinterpret_cast<const float4*>(s_ad)[o4];
        als += a.x*s4.x + a.y*s4.y + a.z*s4.z + a.w*s4.w;
        ald += a.x*d4.x + a.y*d4.y + a.z*d4.z + a.w*d4.w;
    }
    g_als2[n] = als; g_ald2[n] = ald;

    __half2* out = reinterpret_cast<__half2*>(&g_h2h[n * 16]);
#pragma unroll
    for (int o4 = 0; o4 < 4; o4++) {
        out[o4 * 2]     = __floats2half2_rn(h2[o4].x, h2[o4].y);
        out[o4 * 2 + 1] = __floats2half2_rn(h2[o4].z, h2[o4].w);
    }
}

// ===========================================================================
// agg2: FOUR nodes per warp, 8 lanes each, 1 half2 per lane. Unconditional
// loads; __launch_bounds__(256, 8) caps regs.
// ===========================================================================
__global__ __launch_bounds__(256, 8) void agg2_kernel(
    const float* __restrict__ b2, float* __restrict__ out, int N)
{
    int wid = (blockIdx.x * 256 + threadIdx.x) >> 5;
    int lane = threadIdx.x & 31;
    int quad = lane >> 3;
    int l8 = lane & 7;
    int n = wid * 4 + quad;
    if (wid * 4 >= N) return;
    bool nvalid = (n < N);
    int nn = nvalid ? n : (N - 1);
    unsigned gmask = 0xFFu << (quad * 8);

    float ald = __ldg(&g_ald2[nn]);
    int start = g_off[nn];
    int deg = nvalid ? g_deg[nn] : 0;
    int nb = (deg + 7) >> 3;

    int s = __ldg(&g_esrc[start + l8]);
    float w = __expf(leaky(__ldg(&g_als2[s]) + ald));

    float2 acc = make_float2(0.f, 0.f);
    float den = 0.f;
    const unsigned* h2u = reinterpret_cast<const unsigned*>(g_h2h);  // 8 half2 per node
    for (int b = 0; b < nb; b++) {
        int s2 = __ldg(&g_esrc[start + (b + 1) * 8 + l8]);
        float al2 = __ldg(&g_als2[s2]);

        den += w;
#pragma unroll
        for (int j = 0; j < 8; j += 4) {
            int   s0 = __shfl_sync(gmask, s, j,     8);
            int   s1 = __shfl_sync(gmask, s, j + 1, 8);
            int   s2b= __shfl_sync(gmask, s, j + 2, 8);
            int   s3 = __shfl_sync(gmask, s, j + 3, 8);
            float w0 = __shfl_sync(gmask, w, j,     8);
            float w1 = __shfl_sync(gmask, w, j + 1, 8);
            float w2 = __shfl_sync(gmask, w, j + 2, 8);
            float w3 = __shfl_sync(gmask, w, j + 3, 8);
            unsigned v0 = __ldg(&h2u[s0 * 8 + l8]);
            unsigned v1 = __ldg(&h2u[s1 * 8 + l8]);
            unsigned v2b= __ldg(&h2u[s2b* 8 + l8]);
            unsigned v3 = __ldg(&h2u[s3 * 8 + l8]);
            float2 f0 = h2f(v0);
            float2 f1 = h2f(v1);
            float2 f2 = h2f(v2b);
            float2 f3 = h2f(v3);
            acc.x = fmaf(w0, f0.x, acc.x); acc.y = fmaf(w0, f0.y, acc.y);
            acc.x = fmaf(w1, f1.x, acc.x); acc.y = fmaf(w1, f1.y, acc.y);
            acc.x = fmaf(w2, f2.x, acc.x); acc.y = fmaf(w2, f2.y, acc.y);
            acc.x = fmaf(w3, f3.x, acc.x); acc.y = fmaf(w3, f3.y, acc.y);
        }
        s = s2;
        w = __expf(leaky(al2 + ald));
    }
#pragma unroll
    for (int o = 4; o; o >>= 1) den += __shfl_xor_sync(0xffffffffu, den, o, 8);

    float wself = __expf(leaky(__ldg(&g_als2[nn]) + ald));
    den += wself;
    {
        unsigned vo = __ldg(&h2u[nn * 8 + l8]);
        float2 f = h2f(vo);
        acc.x = fmaf(wself, f.x, acc.x);
        acc.y = fmaf(wself, f.y, acc.y);
    }

    float inv = 1.0f / (den + 1e-16f);
    if (nvalid) {
        float2 bv = __ldg(&reinterpret_cast<const float2*>(b2)[l8]);
        float2 r;
        r.x = fmaf(acc.x, inv, bv.x);
        r.y = fmaf(acc.y, inv, bv.y);
        reinterpret_cast<float2*>(&out[n * 16])[l8] = r;
    }
}

// ===========================================================================
extern "C" void kernel_launch(void* const* d_in, const int* in_sizes, int n_in,
                              void* d_out, int out_size)
{
    const float* x   = (const float*)d_in[0];
    const int*   ei  = (const int*)  d_in[1];
    const float* W1  = (const float*)d_in[3];
    const float* as1 = (const float*)d_in[4];
    const float* ad1 = (const float*)d_in[5];
    const float* b1  = (const float*)d_in[6];
    const float* W2  = (const float*)d_in[7];
    const float* as2 = (const float*)d_in[8];
    const float* ad2 = (const float*)d_in[9];
    const float* b2  = (const float*)d_in[10];

    int N = in_sizes[0] / 128;
    int E = in_sizes[1] / 2;
    const int* src = ei;
    const int* dst = ei + E;

    void* p_deg = nullptr; cudaGetSymbolAddress(&p_deg, g_deg);
    cudaMemsetAsync(p_deg, 0, (size_t)(NMAX + 1) * sizeof(int));

    int nblkN = (N + 255) / 256;
    int nblkE4 = (E / 4 + 256) / 256;
    int nscan = (N + SCAN_B - 1) / SCAN_B;

    hist_node1_kernel<<<nblkE4 + nblkN, 256>>>(dst, E, x, W1, as1, ad1, N, nblkE4);
    scan_kernel<<<nscan, SCAN_B>>>(N, nscan);
    permute_kernel<<<nblkE4, 256>>>(src, dst, E);

    int nwarp1 = (((N + 3) / 4) * 32 + 255) / 256;
    agg1_kernel<<<nwarp1, 256>>>(b1, N);

    node2_kernel<<<nblkN, 256>>>(W2, as2, ad2, N);

    int nwarp2 = (((N + 3) / 4) * 32 + 255) / 256;
    agg2_kernel<<<nwarp2, 256>>>(b2, (float*)d_out, N);
}

// round 16
// speedup vs baseline: 1.0331x; 1.0331x over previous
#include <cuda_runtime.h>
#include <cuda_fp16.h>

// Problem constants: N=100000, E=3200000, FEAT=128, HID=32, EMB=16
#define NMAX 100000
#define EMAX 3200000
#define SCAN_B 1024
#define NBLK ((NMAX + SCAN_B - 1) / SCAN_B)   // 98

// ---- scratch (device globals) ----
__device__ __align__(16) __half g_h1h[NMAX * 32];
__device__ float  g_hp1[NMAX * 32];
__device__ float  g_als1[NMAX], g_ald1[NMAX];
__device__ __align__(16) __half g_h2h[NMAX * 16];
__device__ float  g_als2[NMAX], g_ald2[NMAX];

__device__ int g_deg [NMAX + 1];      // [NMAX] = scan arrive counter (memset with deg)
__device__ int g_off [NMAX];
__device__ int g_bsum [NBLK];
__device__ unsigned short g_rank[EMAX];
__device__ int g_esrc[EMAX];

__device__ __forceinline__ float leaky(float a) { return a > 0.0f ? a : 0.2f * a; }
__device__ __forceinline__ float2 h2f(unsigned b) {
    __half2 h = *reinterpret_cast<__half2*>(&b);
    return __half22float2(h);
}

// ===========================================================================
// Fused hist + node1. Blocks [0, histB): degree histogram capturing edge
// ranks (u16). Blocks [histB, ...): node1 GEMM (fp32, one node per thread).
// ===========================================================================
__global__ __launch_bounds__(256) void hist_node1_kernel(
    const int* __restrict__ dst, int E,
    const float* __restrict__ x, const float* __restrict__ W1,
    const float* __restrict__ asrc, const float* __restrict__ adst, int N, int histB)
{
    if ((int)blockIdx.x < histB) {
        int t = blockIdx.x * 256 + threadIdx.x;
        int e = t * 4;
        if (e + 3 < E) {
            int4 d = *reinterpret_cast<const int4*>(dst + e);
            short4 r;
            r.x = (short)atomicAdd(&g_deg[d.x], 1);
            r.y = (short)atomicAdd(&g_deg[d.y], 1);
            r.z = (short)atomicAdd(&g_deg[d.z], 1);
            r.w = (short)atomicAdd(&g_deg[d.w], 1);
            *reinterpret_cast<short4*>(g_rank + e) = r;
        } else {
            for (; e < E; e++) g_rank[e] = (unsigned short)atomicAdd(&g_deg[__ldg(dst + e)], 1);
        }
        return;
    }

    __shared__ float Ws[128 * 32];
    __shared__ float s_as[32], s_ad[32];
    for (int i = threadIdx.x; i < 128 * 32; i += 256) Ws[i] = W1[i];
    if (threadIdx.x < 32) { s_as[threadIdx.x] = asrc[threadIdx.x]; s_ad[threadIdx.x] = adst[threadIdx.x]; }
    __syncthreads();

    int n = (blockIdx.x - histB) * 256 + threadIdx.x;
    if (n >= N) return;

    float4 acc[8];
#pragma unroll
    for (int i = 0; i < 8; i++) acc[i] = make_float4(0.f, 0.f, 0.f, 0.f);

    const float4* xr = reinterpret_cast<const float4*>(x + (size_t)n * 128);
#pragma unroll 4
    for (int k4 = 0; k4 < 32; k4++) {
        float4 xv = __ldg(&xr[k4]);
        float xk[4] = {xv.x, xv.y, xv.z, xv.w};
#pragma unroll
        for (int kk = 0; kk < 4; kk++) {
            const float4* wr = reinterpret_cast<const float4*>(&Ws[(k4 * 4 + kk) * 32]);
            float xs = xk[kk];
#pragma unroll
            for (int c4 = 0; c4 < 8; c4++) {
                float4 w = wr[c4];
                acc[c4].x = fmaf(xs, w.x, acc[c4].x); acc[c4].y = fmaf(xs, w.y, acc[c4].y);
                acc[c4].z = fmaf(xs, w.z, acc[c4].z); acc[c4].w = fmaf(xs, w.w, acc[c4].w);
            }
        }
    }

    float als = 0.f, ald = 0.f;
#pragma unroll
    for (int c4 = 0; c4 < 8; c4++) {
        float4 a  = acc[c4];
        float4 s4 = reinterpret_cast<const float4*>(s_as)[c4];
        float4 d4 = reinterpret_cast<const float4*>(s_ad)[c4];
        als += a.x*s4.x + a.y*s4.y + a.z*s4.z + a.w*s4.w;
        ald += a.x*d4.x + a.y*d4.y + a.z*d4.z + a.w*d4.w;
    }
    g_als1[n] = als; g_ald1[n] = ald;

    __half2* hp = reinterpret_cast<__half2*>(&g_h1h[n * 32]);
#pragma unroll
    for (int c4 = 0; c4 < 8; c4++) {
        hp[c4 * 2]     = __floats2half2_rn(acc[c4].x, acc[c4].y);
        hp[c4 * 2 + 1] = __floats2half2_rn(acc[c4].z, acc[c4].w);
    }
}

// ===========================================================================
// Fused scan: per-block inclusive scan, publish block sum, grid arrive+spin
// (98 blocks <= 148 SMs, all resident -> spin is safe), then each block adds
// its prefix of block sums and writes g_off directly.
// ===========================================================================
__global__ __launch_bounds__(SCAN_B) void scan_kernel(int N, int nb) {
    __shared__ int sh[SCAN_B];
    __shared__ int red[128];
    int b = blockIdx.x;
    int gid = b * SCAN_B + threadIdx.x;
    int v = (gid < N) ? g_deg[gid] : 0;
    sh[threadIdx.x] = v;
    __syncthreads();
#pragma unroll
    for (int o = 1; o < SCAN_B; o <<= 1) {
        int t = (threadIdx.x >= o) ? sh[threadIdx.x - o] : 0;
        __syncthreads();
        sh[threadIdx.x] += t;
        __syncthreads();
    }
    if (threadIdx.x == SCAN_B - 1) {
        g_bsum[b] = sh[SCAN_B - 1];
        __threadfence();
        atomicAdd(&g_deg[NMAX], 1);
    }
    if (threadIdx.x == 0) {
        while (((volatile int*)g_deg)[NMAX] < nb) { }
    }
    __syncthreads();
    __threadfence();   // acquire: order bsum reads after counter observation

    int t = threadIdx.x;
    if (t < 128) red[t] = (t < b) ? g_bsum[t] : 0;
    __syncthreads();
    if (t < 64) red[t] += red[t + 64];
    __syncthreads();
    if (t < 32) {
        int s = red[t] + red[t + 32];
#pragma unroll
        for (int o = 16; o; o >>= 1) s += __shfl_xor_sync(0xffffffffu, s, o);
        if (t == 0) red[0] = s;
    }
    __syncthreads();
    int prev = red[0];

    if (gid < N) g_off[gid] = prev + sh[threadIdx.x] - v;
}

// ===========================================================================
// permute: atomic-free, 8 edges/thread (2x int4 groups -> 8 gathers in
// flight per thread, amortized index math).
// ===========================================================================
__global__ __launch_bounds__(256) void permute_kernel(
    const int* __restrict__ src, const int* __restrict__ dst, int E)
{
    int t = blockIdx.x * 256 + threadIdx.x;
    int e = t * 8;
    if (e + 7 < E) {
        int4 dA = *reinterpret_cast<const int4*>(dst + e);
        int4 dB = *reinterpret_cast<const int4*>(dst + e + 4);
        short4 rA = *reinterpret_cast<const short4*>(g_rank + e);
        short4 rB = *reinterpret_cast<const short4*>(g_rank + e + 4);
        int4 sA = *reinterpret_cast<const int4*>(src + e);
        int4 sB = *reinterpret_cast<const int4*>(src + e + 4);
        int p0 = __ldg(&g_off[dA.x]) + (int)(unsigned short)rA.x;
        int p1 = __ldg(&g_off[dA.y]) + (int)(unsigned short)rA.y;
        int p2 = __ldg(&g_off[dA.z]) + (int)(unsigned short)rA.z;
        int p3 = __ldg(&g_off[dA.w]) + (int)(unsigned short)rA.w;
        int p4 = __ldg(&g_off[dB.x]) + (int)(unsigned short)rB.x;
        int p5 = __ldg(&g_off[dB.y]) + (int)(unsigned short)rB.y;
        int p6 = __ldg(&g_off[dB.z]) + (int)(unsigned short)rB.z;
        int p7 = __ldg(&g_off[dB.w]) + (int)(unsigned short)rB.w;
        g_esrc[p0] = sA.x;
        g_esrc[p1] = sA.y;
        g_esrc[p2] = sA.z;
        g_esrc[p3] = sA.w;
        g_esrc[p4] = sB.x;
        g_esrc[p5] = sB.y;
        g_esrc[p6] = sB.z;
        g_esrc[p7] = sB.w;
    } else {
        for (; e < E; e++) {
            int d = __ldg(dst + e);
            g_esrc[__ldg(&g_off[d]) + (int)g_rank[e]] = __ldg(src + e);
        }
    }
}

// ===========================================================================
// agg1: layer-1 aggregate. FOUR nodes per warp, 8 lanes each. Per-GROUP loop
// count (divergent groups; no shfl-max) with group-local shfl masks; feature
// loads predicated on w!=0 -> zero wasted wavefronts. (R13 verbatim)
// ===========================================================================
__global__ __launch_bounds__(256) void agg1_kernel(const float* __restrict__ b1, int N)
{
    int wid = (blockIdx.x * 256 + threadIdx.x) >> 5;
    int lane = threadIdx.x & 31;
    int quad = lane >> 3;
    int l8 = lane & 7;
    int n = wid * 4 + quad;
    if (wid * 4 >= N) return;
    bool nvalid = (n < N);
    int nn = nvalid ? n : (N - 1);
    unsigned gmask = 0xFFu << (quad * 8);

    float ald = __ldg(&g_ald1[nn]);
    int start = g_off[nn];
    int deg = nvalid ? g_deg[nn] : 0;
    int end = start + deg;
    int nb = (deg + 7) >> 3;          // per-group trip count

    int s = 0; float w;
    {
        int idx = start + l8;
        bool v = idx < end;
        float al = 0.f;
        if (v) { s = __ldg(&g_esrc[idx]); al = __ldg(&g_als1[s]); }
        w = v ? __expf(leaky(al + ald)) : 0.f;
    }

    float4 acc = make_float4(0.f, 0.f, 0.f, 0.f);
    float den = 0.f;
    const uint2* h1u = reinterpret_cast<const uint2*>(g_h1h);
    for (int b = 0; b < nb; b++) {
        int idx2 = start + (b + 1) * 8 + l8;
        bool v2 = idx2 < end;
        int s2 = 0; float al2 = 0.f;
        if (v2) { s2 = __ldg(&g_esrc[idx2]); al2 = __ldg(&g_als1[s2]); }

        den += w;
#pragma unroll
        for (int j = 0; j < 8; j += 4) {
            int   s0 = __shfl_sync(gmask, s, j,     8);
            int   s1 = __shfl_sync(gmask, s, j + 1, 8);
            int   s2b= __shfl_sync(gmask, s, j + 2, 8);
            int   s3 = __shfl_sync(gmask, s, j + 3, 8);
            float w0 = __shfl_sync(gmask, w, j,     8);
            float w1 = __shfl_sync(gmask, w, j + 1, 8);
            float w2 = __shfl_sync(gmask, w, j + 2, 8);
            float w3 = __shfl_sync(gmask, w, j + 3, 8);
            uint2 z = make_uint2(0u, 0u);
            uint2 v0 = (w0 != 0.f) ? __ldg(&h1u[s0 * 8 + l8]) : z;
            uint2 v1 = (w1 != 0.f) ? __ldg(&h1u[s1 * 8 + l8]) : z;
            uint2 v2b= (w2 != 0.f) ? __ldg(&h1u[s2b* 8 + l8]) : z;
            uint2 v3 = (w3 != 0.f) ? __ldg(&h1u[s3 * 8 + l8]) : z;
            float2 f0a = h2f(v0.x), f0b = h2f(v0.y);
            float2 f1a = h2f(v1.x), f1b = h2f(v1.y);
            float2 f2a = h2f(v2b.x), f2b = h2f(v2b.y);
            float2 f3a = h2f(v3.x), f3b = h2f(v3.y);
            acc.x = fmaf(w0, f0a.x, acc.x); acc.y = fmaf(w0, f0a.y, acc.y);
            acc.z = fmaf(w0, f0b.x, acc.z); acc.w = fmaf(w0, f0b.y, acc.w);
            acc.x = fmaf(w1, f1a.x, acc.x); acc.y = fmaf(w1, f1a.y, acc.y);
            acc.z = fmaf(w1, f1b.x, acc.z); acc.w = fmaf(w1, f1b.y, acc.w);
            acc.x = fmaf(w2, f2a.x, acc.x); acc.y = fmaf(w2, f2a.y, acc.y);
            acc.z = fmaf(w2, f2b.x, acc.z); acc.w = fmaf(w2, f2b.y, acc.w);
            acc.x = fmaf(w3, f3a.x, acc.x); acc.y = fmaf(w3, f3a.y, acc.y);
            acc.z = fmaf(w3, f3b.x, acc.z); acc.w = fmaf(w3, f3b.y, acc.w);
        }
        s = s2;
        w = v2 ? __expf(leaky(al2 + ald)) : 0.f;
    }
#pragma unroll
    for (int o = 4; o; o >>= 1) den += __shfl_xor_sync(0xffffffffu, den, o, 8);

    float wself = __expf(leaky(__ldg(&g_als1[nn]) + ald));
    den += wself;
    {
        uint2 vo = __ldg(&h1u[nn * 8 + l8]);
        float2 fa = h2f(vo.x), fb = h2f(vo.y);
        acc.x = fmaf(wself, fa.x, acc.x); acc.y = fmaf(wself, fa.y, acc.y);
        acc.z = fmaf(wself, fb.x, acc.z); acc.w = fmaf(wself, fb.y, acc.w);
    }

    float inv = 1.0f / (den + 1e-16f);
    if (nvalid) {
        float4 bv = __ldg(&reinterpret_cast<const float4*>(b1)[l8]);
        float4 r;
        r.x = fmaxf(fmaf(acc.x, inv, bv.x), 0.f);
        r.y = fmaxf(fmaf(acc.y, inv, bv.y), 0.f);
        r.z = fmaxf(fmaf(acc.z, inv, bv.z), 0.f);
        r.w = fmaxf(fmaf(acc.w, inv, bv.w), 0.f);
        reinterpret_cast<float4*>(&g_hp1[n * 32])[l8] = r;
    }
}

// ===========================================================================
// node2: h2 = h' @ W2 (-> fp16); al_s2/al_d2
// ===========================================================================
__global__ __launch_bounds__(256) void node2_kernel(
    const float* __restrict__ W2,
    const float* __restrict__ asrc, const float* __restrict__ adst, int N)
{
    __shared__ float Ws[32 * 16];
    __shared__ float s_as[16], s_ad[16];
    for (int i = threadIdx.x; i < 32 * 16; i += 256) Ws[i] = W2[i];
    if (threadIdx.x < 16) { s_as[threadIdx.x] = asrc[threadIdx.x]; s_ad[threadIdx.x] = adst[threadIdx.x]; }
    __syncthreads();

    int n = blockIdx.x * 256 + threadIdx.x;
    if (n >= N) return;

    float4 h2[4];
#pragma unroll
    for (int i = 0; i < 4; i++) h2[i] = make_float4(0.f, 0.f, 0.f, 0.f);

    const float4* hp = reinterpret_cast<const float4*>(&g_hp1[n * 32]);
#pragma unroll
    for (int c4 = 0; c4 < 8; c4++) {
        float4 xv = hp[c4];
        float xk[4] = {xv.x, xv.y, xv.z, xv.w};
#pragma unroll
        for (int kk = 0; kk < 4; kk++) {
            const float4* wr = reinterpret_cast<const float4*>(&Ws[(c4 * 4 + kk) * 16]);
            float xs = xk[kk];
#pragma unroll
            for (int o4 = 0; o4 < 4; o4++) {
                float4 w = wr[o4];
                h2[o4].x = fmaf(xs, w.x, h2[o4].x); h2[o4].y = fmaf(xs, w.y, h2[o4].y);
                h2[o4].z = fmaf(xs, w.z, h2[o4].z); h2[o4].w = fmaf(xs, w.w, h2[o4].w);
            }
        }
    }

    float als = 0.f, ald = 0.f;
#pragma unroll
    for (int o4 = 0; o4 < 4; o4++) {
        float4 a  = h2[o4];
        float4 s4 = reinterpret_cast<const float4*>(s_as)[o4];
        float4 d4 = reinterpret_cast<const float4*>(s_ad)[o4];
        als += a.x*s4.x + a.y*s4.y + a.z*s4.z + a.w*s4.w;
        ald += a.x*d4.x + a.y*d4.y + a.z*d4.z + a.w*d4.w;
    }
    g_als2[n] = als; g_ald2[n] = ald;

    __half2* out = reinterpret_cast<__half2*>(&g_h2h[n * 16]);
#pragma unroll
    for (int o4 = 0; o4 < 4; o4++) {
        out[o4 * 2]     = __floats2half2_rn(h2[o4].x, h2[o4].y);
        out[o4 * 2 + 1] = __floats2half2_rn(h2[o4].z, h2[o4].w);
    }
}

// ===========================================================================
// agg2: layer-2 aggregate + output. EIGHT nodes per warp, 4 lanes each.
// Per-group loop count, group-local masks, predicated loads. (R13 verbatim)
// ===========================================================================
__global__ __launch_bounds__(256) void agg2_kernel(
    const float* __restrict__ b2, float* __restrict__ out, int N)
{
    int wid = (blockIdx.x * 256 + threadIdx.x) >> 5;
    int lane = threadIdx.x & 31;
    int oct = lane >> 2;
    int l4 = lane & 3;
    int n = wid * 8 + oct;
    if (wid * 8 >= N) return;
    bool nvalid = (n < N);
    int nn = nvalid ? n : (N - 1);
    unsigned gmask = 0xFu << (oct * 4);

    float ald = __ldg(&g_ald2[nn]);
    int start = g_off[nn];
    int deg = nvalid ? g_deg[nn] : 0;
    int end = start + deg;
    int nb = (deg + 3) >> 2;          // per-group trip count

    int s = 0; float w;
    {
        int idx = start + l4;
        bool v = idx < end;
        float al = 0.f;
        if (v) { s = __ldg(&g_esrc[idx]); al = __ldg(&g_als2[s]); }
        w = v ? __expf(leaky(al + ald)) : 0.f;
    }

    float4 acc = make_float4(0.f, 0.f, 0.f, 0.f);
    float den = 0.f;
    const uint2* h2u = reinterpret_cast<const uint2*>(g_h2h);
    for (int b = 0; b < nb; b++) {
        int idx2 = start + (b + 1) * 4 + l4;
        bool v2 = idx2 < end;
        int s2 = 0; float al2 = 0.f;
        if (v2) { s2 = __ldg(&g_esrc[idx2]); al2 = __ldg(&g_als2[s2]); }

        den += w;
        {
            int   s0 = __shfl_sync(gmask, s, 0, 4);
            int   s1 = __shfl_sync(gmask, s, 1, 4);
            int   s2b= __shfl_sync(gmask, s, 2, 4);
            int   s3 = __shfl_sync(gmask, s, 3, 4);
            float w0 = __shfl_sync(gmask, w, 0, 4);
            float w1 = __shfl_sync(gmask, w, 1, 4);
            float w2 = __shfl_sync(gmask, w, 2, 4);
            float w3 = __shfl_sync(gmask, w, 3, 4);
            uint2 z = make_uint2(0u, 0u);
            uint2 v0 = (w0 != 0.f) ? __ldg(&h2u[s0 * 4 + l4]) : z;
            uint2 v1 = (w1 != 0.f) ? __ldg(&h2u[s1 * 4 + l4]) : z;
            uint2 v2b= (w2 != 0.f) ? __ldg(&h2u[s2b* 4 + l4]) : z;
            uint2 v3 = (w3 != 0.f) ? __ldg(&h2u[s3 * 4 + l4]) : z;
            float2 f0a = h2f(v0.x), f0b = h2f(v0.y);
            float2 f1a = h2f(v1.x), f1b = h2f(v1.y);
            float2 f2a = h2f(v2b.x), f2b = h2f(v2b.y);
            float2 f3a = h2f(v3.x), f3b = h2f(v3.y);
            acc.x = fmaf(w0, f0a.x, acc.x); acc.y = fmaf(w0, f0a.y, acc.y);
            acc.z = fmaf(w0, f0b.x, acc.z); acc.w = fmaf(w0, f0b.y, acc.w);
            acc.x = fmaf(w1, f1a.x, acc.x); acc.y = fmaf(w1, f1a.y, acc.y);
            acc.z = fmaf(w1, f1b.x, acc.z); acc.w = fmaf(w1, f1b.y, acc.w);
            acc.x = fmaf(w2, f2a.x, acc.x); acc.y = fmaf(w2, f2a.y, acc.y);
            acc.z = fmaf(w2, f2b.x, acc.z); acc.w = fmaf(w2, f2b.y, acc.w);
            acc.x = fmaf(w3, f3a.x, acc.x); acc.y = fmaf(w3, f3a.y, acc.y);
            acc.z = fmaf(w3, f3b.x, acc.z); acc.w = fmaf(w3, f3b.y, acc.w);
        }
        s = s2;
        w = v2 ? __expf(leaky(al2 + ald)) : 0.f;
    }
#pragma unroll
    for (int o = 2; o; o >>= 1) den += __shfl_xor_sync(0xffffffffu, den, o, 4);

    float wself = __expf(leaky(__ldg(&g_als2[nn]) + ald));
    den += wself;
    {
        uint2 vo = __ldg(&h2u[nn * 4 + l4]);
        float2 fa = h2f(vo.x), fb = h2f(vo.y);
        acc.x = fmaf(wself, fa.x, acc.x); acc.y = fmaf(wself, fa.y, acc.y);
        acc.z = fmaf(wself, fb.x, acc.z); acc.w = fmaf(wself, fb.y, acc.w);
    }

    float inv = 1.0f / (den + 1e-16f);
    if (nvalid) {
        float4 bv = __ldg(&reinterpret_cast<const float4*>(b2)[l4]);
        float4 r;
        r.x = fmaf(acc.x, inv, bv.x);
        r.y = fmaf(acc.y, inv, bv.y);
        r.z = fmaf(acc.z, inv, bv.z);
        r.w = fmaf(acc.w, inv, bv.w);
        reinterpret_cast<float4*>(&out[n * 16])[l4] = r;
    }
}

// ===========================================================================
extern "C" void kernel_launch(void* const* d_in, const int* in_sizes, int n_in,
                              void* d_out, int out_size)
{
    const float* x   = (const float*)d_in[0];
    const int*   ei  = (const int*)  d_in[1];
    const float* W1  = (const float*)d_in[3];
    const float* as1 = (const float*)d_in[4];
    const float* ad1 = (const float*)d_in[5];
    const float* b1  = (const float*)d_in[6];
    const float* W2  = (const float*)d_in[7];
    const float* as2 = (const float*)d_in[8];
    const float* ad2 = (const float*)d_in[9];
    const float* b2  = (const float*)d_in[10];

    int N = in_sizes[0] / 128;
    int E = in_sizes[1] / 2;
    const int* src = ei;
    const int* dst = ei + E;

    // single memset covers deg[NMAX] histogram + scan arrive counter
    void* p_deg = nullptr; cudaGetSymbolAddress(&p_deg, g_deg);
    cudaMemsetAsync(p_deg, 0, (size_t)(NMAX + 1) * sizeof(int));

    int nblkN = (N + 255) / 256;
    int nblkE4 = (E / 4 + 256) / 256;
    int nblkE8 = (E / 8 + 256) / 256;
    int nscan = (N + SCAN_B - 1) / SCAN_B;   // 98 <= 148: all-resident spin safe

    hist_node1_kernel<<<nblkE4 + nblkN, 256>>>(dst, E, x, W1, as1, ad1, N, nblkE4);
    scan_kernel<<<nscan, SCAN_B>>>(N, nscan);
    permute_kernel<<<nblkE8, 256>>>(src, dst, E);

    int nwarp1 = (((N + 3) / 4) * 32 + 255) / 256;
    agg1_kernel<<<nwarp1, 256>>>(b1, N);

    node2_kernel<<<nblkN, 256>>>(W2, as2, ad2, N);

    int nwarp2 = (((N + 7) / 8) * 32 + 255) / 256;
    agg2_kernel<<<nwarp2, 256>>>(b2, (float*)d_out, N);
}